// round 1
// baseline (speedup 1.0000x reference)
#include <cuda_runtime.h>
#include <math.h>

#define Bn 4
#define Tn 2048
#define Dn 1024
#define Hn 16
#define HDn 64
#define MROWS (Bn*Tn)      // 8192
#define QKVN (3*Dn)        // 3072

// Scratch (static device allocations are the sanctioned mechanism)
__device__ float g_qkv[(size_t)MROWS * QKVN];   // 100.7 MB
__device__ float g_attn[(size_t)MROWS * Dn];    // 33.6 MB

// ---------------------------------------------------------------------------
// SGEMM: C[M,N] = A[M,K] @ B[K,N] (+ bias). 128x128 block tile, 8x8/thread.
// ---------------------------------------------------------------------------
template <int WITH_BIAS>
__global__ void __launch_bounds__(256) sgemm_kernel(
    const float* __restrict__ A, const float* __restrict__ Bm,
    const float* __restrict__ bias, float* __restrict__ C,
    int M, int N, int K)
{
    __shared__ float As[16][132];   // A transposed: As[k][m], padded
    __shared__ float Bs[16][128];

    const int tid = threadIdx.x;
    const int bm = blockIdx.y * 128;
    const int bn = blockIdx.x * 128;

    const int ty = tid >> 4;        // 0..15
    const int tx = tid & 15;        // 0..15

    const int aRow = tid >> 2;      // 0..63
    const int aCol = (tid & 3) * 4; // 0,4,8,12
    const int bRow = tid >> 5;      // 0..7
    const int bCol = (tid & 31) * 4;

    float acc[8][8];
    #pragma unroll
    for (int i = 0; i < 8; i++)
        #pragma unroll
        for (int j = 0; j < 8; j++) acc[i][j] = 0.f;

    for (int k0 = 0; k0 < K; k0 += 16) {
        #pragma unroll
        for (int it = 0; it < 2; it++) {
            float4 v = *(const float4*)&A[(size_t)(bm + aRow + it*64) * K + k0 + aCol];
            As[aCol+0][aRow + it*64] = v.x;
            As[aCol+1][aRow + it*64] = v.y;
            As[aCol+2][aRow + it*64] = v.z;
            As[aCol+3][aRow + it*64] = v.w;
        }
        #pragma unroll
        for (int it = 0; it < 2; it++) {
            float4 v = *(const float4*)&Bm[(size_t)(k0 + bRow + it*8) * N + bn + bCol];
            *(float4*)&Bs[bRow + it*8][bCol] = v;
        }
        __syncthreads();

        #pragma unroll
        for (int kk = 0; kk < 16; kk++) {
            float a[8], b[8];
            *(float4*)&a[0] = *(const float4*)&As[kk][ty*8];
            *(float4*)&a[4] = *(const float4*)&As[kk][ty*8+4];
            *(float4*)&b[0] = *(const float4*)&Bs[kk][tx*8];
            *(float4*)&b[4] = *(const float4*)&Bs[kk][tx*8+4];
            #pragma unroll
            for (int i = 0; i < 8; i++)
                #pragma unroll
                for (int j = 0; j < 8; j++)
                    acc[i][j] += a[i] * b[j];
        }
        __syncthreads();
    }

    #pragma unroll
    for (int i = 0; i < 8; i++) {
        const size_t row = (size_t)(bm + ty*8 + i);
        #pragma unroll
        for (int j4 = 0; j4 < 2; j4++) {
            const int col = bn + tx*8 + j4*4;
            float4 v;
            v.x = acc[i][j4*4+0]; v.y = acc[i][j4*4+1];
            v.z = acc[i][j4*4+2]; v.w = acc[i][j4*4+3];
            if (WITH_BIAS) {
                v.x += bias[col+0]; v.y += bias[col+1];
                v.z += bias[col+2]; v.w += bias[col+3];
            }
            *(float4*)&C[row * N + col] = v;
        }
    }
}

// ---------------------------------------------------------------------------
// RoPE + L2 normalize q and k, in place inside qkv. One warp per (b,t,h,q|k).
// ---------------------------------------------------------------------------
__global__ void __launch_bounds__(256) rope_norm_kernel(float* __restrict__ qkv)
{
    const int gw = (blockIdx.x * blockDim.x + threadIdx.x) >> 5;
    const int lane = threadIdx.x & 31;
    // gw = b*(T*H*2) + t*(H*2) + h*2 + which   (2*H = 32, 2*H*T = 65536)
    const int which = gw & 1;
    const int h = (gw >> 1) & (Hn - 1);
    const int t = (gw >> 5) & (Tn - 1);
    const int b = gw >> 16;

    float* p = qkv + (size_t)(b*Tn + t) * QKVN + which*Dn + h*HDn;

    const float inv_freq = powf(10000.f, -(float)lane * (1.f/32.f));
    const float ang = (float)t * inv_freq;
    float s, c;
    sincosf(ang, &s, &c);

    const float x1 = p[lane];
    const float x2 = p[lane + 32];
    const float r1 = x1*c - x2*s;
    const float r2 = x1*s + x2*c;

    float ss = r1*r1 + r2*r2;
    #pragma unroll
    for (int off = 16; off; off >>= 1)
        ss += __shfl_xor_sync(0xffffffffu, ss, off);

    const float inv = rsqrtf(ss + 1e-6f);
    p[lane]      = r1 * inv;
    p[lane + 32] = r2 * inv;
}

// ---------------------------------------------------------------------------
// Flash attention, fp32. One block = 64 query rows of one (b,h).
// smem: Qs[64][68], KVs[64][68] (K then V), Ps[64][68]. 256 threads.
// Thread (r = tid/4, c4 = tid&3): 16 scores (keys c4+4k), 16 out cols
// (cols c4*4 + 16*jj + i).
// ---------------------------------------------------------------------------
#define PITCH 68
#define SMEM_BYTES (3 * 64 * PITCH * 4)

__global__ void __launch_bounds__(256) attn_kernel(
    const float* __restrict__ qkv, float* __restrict__ outp)
{
    extern __shared__ float sm[];
    float* Qs  = sm;
    float* KVs = sm + 64*PITCH;
    float* Ps  = sm + 2*64*PITCH;

    const int tid = threadIdx.x;
    const int qt = blockIdx.x & 31;
    const int h  = (blockIdx.x >> 5) & (Hn - 1);
    const int b  = blockIdx.x >> 9;
    const int q0 = qt * 64;

    const float* qbase = qkv + (size_t)(b*Tn) * QKVN + h*HDn;
    const float* kbase = qbase + Dn;
    const float* vbase = qbase + 2*Dn;

    const int lr = tid >> 2;        // load row 0..63
    const int lc = (tid & 3) * 4;   // load col offset

    // Load Q tile (pre-scaled by 1/sqrt(HD))
    {
        const float* src = qbase + (size_t)(q0 + lr) * QKVN;
        #pragma unroll
        for (int j = 0; j < 4; j++) {
            float4 v = *(const float4*)&src[lc + j*16];
            v.x *= 0.125f; v.y *= 0.125f; v.z *= 0.125f; v.w *= 0.125f;
            *(float4*)&Qs[lr*PITCH + lc + j*16] = v;
        }
    }

    const int r  = tid >> 2;        // query row this thread works on
    const int c4 = tid & 3;

    float m = -1e30f, l = 0.f;
    float o[16];
    #pragma unroll
    for (int j = 0; j < 16; j++) o[j] = 0.f;

    for (int kt = 0; kt < Tn/64; kt++) {
        __syncthreads();  // prior V reads complete before KVs overwrite
        {
            const float* src = kbase + (size_t)(kt*64 + lr) * QKVN;
            #pragma unroll
            for (int j = 0; j < 4; j++)
                *(float4*)&KVs[lr*PITCH + lc + j*16] = *(const float4*)&src[lc + j*16];
        }
        __syncthreads();

        // ---- scores: sc[kk] = q_row . k_{c4+4kk} ----
        float sc[16];
        #pragma unroll
        for (int kk = 0; kk < 16; kk++) sc[kk] = 0.f;
        #pragma unroll 4
        for (int d4 = 0; d4 < 16; d4++) {
            const float4 q4 = *(const float4*)&Qs[r*PITCH + d4*4];
            #pragma unroll
            for (int kk = 0; kk < 16; kk++) {
                const float4 k4 = *(const float4*)&KVs[(c4 + kk*4)*PITCH + d4*4];
                sc[kk] += q4.x*k4.x + q4.y*k4.y + q4.z*k4.z + q4.w*k4.w;
            }
        }

        // ---- online softmax ----
        float tmax = sc[0];
        #pragma unroll
        for (int kk = 1; kk < 16; kk++) tmax = fmaxf(tmax, sc[kk]);
        tmax = fmaxf(tmax, __shfl_xor_sync(0xffffffffu, tmax, 1, 4));
        tmax = fmaxf(tmax, __shfl_xor_sync(0xffffffffu, tmax, 2, 4));

        const float mnew = fmaxf(m, tmax);
        const float corr = __expf(m - mnew);
        float lsum = 0.f;
        #pragma unroll
        for (int kk = 0; kk < 16; kk++) {
            const float p = __expf(sc[kk] - mnew);
            lsum += p;
            Ps[r*PITCH + c4 + kk*4] = p;
        }
        lsum += __shfl_xor_sync(0xffffffffu, lsum, 1, 4);
        lsum += __shfl_xor_sync(0xffffffffu, lsum, 2, 4);
        l = l * corr + lsum;
        m = mnew;
        #pragma unroll
        for (int j = 0; j < 16; j++) o[j] *= corr;

        __syncthreads();  // K reads done + Ps visible
        {
            const float* src = vbase + (size_t)(kt*64 + lr) * QKVN;
            #pragma unroll
            for (int j = 0; j < 4; j++)
                *(float4*)&KVs[lr*PITCH + lc + j*16] = *(const float4*)&src[lc + j*16];
        }
        __syncthreads();

        // ---- o += P @ V ----
        #pragma unroll 8
        for (int s = 0; s < 64; s++) {
            const float p = Ps[r*PITCH + s];
            #pragma unroll
            for (int jj = 0; jj < 4; jj++) {
                const float4 v4 = *(const float4*)&KVs[s*PITCH + c4*4 + jj*16];
                o[jj*4+0] += p * v4.x;
                o[jj*4+1] += p * v4.y;
                o[jj*4+2] += p * v4.z;
                o[jj*4+3] += p * v4.w;
            }
        }
    }

    const float inv = 1.f / l;
    float* orow = outp + (size_t)(b*Tn + q0 + r) * Dn + h*HDn;
    #pragma unroll
    for (int jj = 0; jj < 4; jj++) {
        float4 v;
        v.x = o[jj*4+0]*inv; v.y = o[jj*4+1]*inv;
        v.z = o[jj*4+2]*inv; v.w = o[jj*4+3]*inv;
        *(float4*)&orow[c4*4 + jj*16] = v;
    }
}

// ---------------------------------------------------------------------------
extern "C" void kernel_launch(void* const* d_in, const int* in_sizes, int n_in,
                              void* d_out, int out_size)
{
    const float* x    = (const float*)d_in[0];
    const float* Wqkv = (const float*)d_in[1];
    const float* Wo   = (const float*)d_in[2];
    const float* bo   = (const float*)d_in[3];
    float* out = (float*)d_out;

    float* qkv = nullptr;
    float* att = nullptr;
    cudaGetSymbolAddress((void**)&qkv, g_qkv);
    cudaGetSymbolAddress((void**)&att, g_attn);

    cudaFuncSetAttribute(attn_kernel,
                         cudaFuncAttributeMaxDynamicSharedMemorySize, SMEM_BYTES);

    // 1) qkv = x @ Wqkv
    {
        dim3 grid(QKVN/128, MROWS/128);
        sgemm_kernel<0><<<grid, 256>>>(x, Wqkv, nullptr, qkv, MROWS, QKVN, Dn);
    }
    // 2) RoPE + L2 norm on q,k
    {
        int warps = Bn*Tn*Hn*2;           // 262144
        rope_norm_kernel<<<warps/8, 256>>>(qkv);
    }
    // 3) attention
    {
        dim3 grid(Bn * Hn * (Tn/64));     // 2048
        attn_kernel<<<grid, 256, SMEM_BYTES>>>(qkv, att);
    }
    // 4) out = att @ Wo + bo
    {
        dim3 grid(Dn/128, MROWS/128);
        sgemm_kernel<1><<<grid, 256>>>(att, Wo, bo, out, MROWS, Dn, Dn);
    }
}

// round 3
// speedup vs baseline: 2.2640x; 2.2640x over previous
#include <cuda_runtime.h>
#include <mma.h>
#include <math.h>
#include <stdint.h>

using namespace nvcuda;

#define Bn 4
#define Tn 2048
#define Dn 1024
#define Hn 16
#define HDn 64
#define MROWS (Bn*Tn)      // 8192
#define QKVN (3*Dn)        // 3072

// Scratch
__device__ float g_qkv[(size_t)MROWS * QKVN];   // 100.7 MB
__device__ float g_attn[(size_t)MROWS * Dn];    // 33.6 MB

__device__ __forceinline__ float to_tf32(float x) {
    uint32_t u;
    asm("cvt.rna.tf32.f32 %0, %1;" : "=r"(u) : "f"(x));
    return __uint_as_float(u);
}

// ---------------------------------------------------------------------------
// TF32 tensor-core GEMM: C[M,N] = A[M,K] @ B[K,N]. 128x128 tile, 8 warps.
// Warp tile 64x32 = 4x2 wmma(16x16) frags. K-tile = 16 (two k=8 steps).
// ---------------------------------------------------------------------------
__global__ void __launch_bounds__(256) gemm_tf32(
    const float* __restrict__ A, const float* __restrict__ Bm,
    float* __restrict__ C, int M, int N, int K)
{
    __shared__ float As[128][24];   // row-major [m][k], pad to 24
    __shared__ float Bs[16][136];   // row-major [k][n], pad to 136

    const int tid = threadIdx.x;
    const int bm = blockIdx.y * 128;
    const int bn = blockIdx.x * 128;
    const int w  = tid >> 5;
    const int wm = (w >> 2) * 64;   // 0 or 64
    const int wn = (w & 3) * 32;    // 0,32,64,96

    wmma::fragment<wmma::accumulator, 16, 16, 8, float> acc[4][2];
    #pragma unroll
    for (int i = 0; i < 4; i++)
        #pragma unroll
        for (int j = 0; j < 2; j++) wmma::fill_fragment(acc[i][j], 0.f);

    const int aRow = tid >> 1;         // 0..127
    const int aCol = (tid & 1) * 8;    // 0 or 8
    const int bRow = tid >> 4;         // 0..15
    const int bCol = (tid & 15) * 8;   // 0..120

    for (int k0 = 0; k0 < K; k0 += 16) {
        {
            const float* src = &A[(size_t)(bm + aRow) * K + k0 + aCol];
            float4 v0 = *(const float4*)(src);
            float4 v1 = *(const float4*)(src + 4);
            As[aRow][aCol+0] = to_tf32(v0.x); As[aRow][aCol+1] = to_tf32(v0.y);
            As[aRow][aCol+2] = to_tf32(v0.z); As[aRow][aCol+3] = to_tf32(v0.w);
            As[aRow][aCol+4] = to_tf32(v1.x); As[aRow][aCol+5] = to_tf32(v1.y);
            As[aRow][aCol+6] = to_tf32(v1.z); As[aRow][aCol+7] = to_tf32(v1.w);
        }
        {
            const float* src = &Bm[(size_t)(k0 + bRow) * N + bn + bCol];
            float4 v0 = *(const float4*)(src);
            float4 v1 = *(const float4*)(src + 4);
            Bs[bRow][bCol+0] = to_tf32(v0.x); Bs[bRow][bCol+1] = to_tf32(v0.y);
            Bs[bRow][bCol+2] = to_tf32(v0.z); Bs[bRow][bCol+3] = to_tf32(v0.w);
            Bs[bRow][bCol+4] = to_tf32(v1.x); Bs[bRow][bCol+5] = to_tf32(v1.y);
            Bs[bRow][bCol+6] = to_tf32(v1.z); Bs[bRow][bCol+7] = to_tf32(v1.w);
        }
        __syncthreads();

        #pragma unroll
        for (int kk = 0; kk < 16; kk += 8) {
            wmma::fragment<wmma::matrix_a, 16, 16, 8, wmma::precision::tf32, wmma::row_major> af[4];
            wmma::fragment<wmma::matrix_b, 16, 16, 8, wmma::precision::tf32, wmma::row_major> bf[2];
            #pragma unroll
            for (int i = 0; i < 4; i++)
                wmma::load_matrix_sync(af[i], &As[wm + i*16][kk], 24);
            #pragma unroll
            for (int j = 0; j < 2; j++)
                wmma::load_matrix_sync(bf[j], &Bs[kk][wn + j*16], 136);
            #pragma unroll
            for (int i = 0; i < 4; i++)
                #pragma unroll
                for (int j = 0; j < 2; j++)
                    wmma::mma_sync(acc[i][j], af[i], bf[j], acc[i][j]);
        }
        __syncthreads();
    }

    #pragma unroll
    for (int i = 0; i < 4; i++)
        #pragma unroll
        for (int j = 0; j < 2; j++)
            wmma::store_matrix_sync(&C[(size_t)(bm + wm + i*16) * N + bn + wn + j*16],
                                    acc[i][j], N, wmma::mem_row_major);
}

// Bias add: out[m][n] += bias[n]
__global__ void __launch_bounds__(256) bias_add_kernel(
    float* __restrict__ out, const float* __restrict__ bias, int total4, int N)
{
    int idx = blockIdx.x * blockDim.x + threadIdx.x;
    if (idx >= total4) return;
    int col = (idx * 4) & (N - 1);           // N power of 2
    float4 v = *(float4*)&out[idx * 4];
    v.x += bias[col+0]; v.y += bias[col+1];
    v.z += bias[col+2]; v.w += bias[col+3];
    *(float4*)&out[idx * 4] = v;
}

// ---------------------------------------------------------------------------
// RoPE + L2 normalize q and k, in place inside qkv. One warp per (b,t,h,q|k).
// ---------------------------------------------------------------------------
__global__ void __launch_bounds__(256) rope_norm_kernel(float* __restrict__ qkv)
{
    const int gw = (blockIdx.x * blockDim.x + threadIdx.x) >> 5;
    const int lane = threadIdx.x & 31;
    const int which = gw & 1;
    const int h = (gw >> 1) & (Hn - 1);
    const int t = (gw >> 5) & (Tn - 1);
    const int b = gw >> 16;

    float* p = qkv + (size_t)(b*Tn + t) * QKVN + which*Dn + h*HDn;

    const float inv_freq = powf(10000.f, -(float)lane * (1.f/32.f));
    const float ang = (float)t * inv_freq;
    float s, c;
    sincosf(ang, &s, &c);

    const float x1 = p[lane];
    const float x2 = p[lane + 32];
    const float r1 = x1*c - x2*s;
    const float r2 = x1*s + x2*c;

    float ss = r1*r1 + r2*r2;
    #pragma unroll
    for (int off = 16; off; off >>= 1)
        ss += __shfl_xor_sync(0xffffffffu, ss, off);

    const float inv = rsqrtf(ss + 1e-6f);
    p[lane]      = r1 * inv;
    p[lane + 32] = r2 * inv;
}

// ---------------------------------------------------------------------------
// Tensor-core flash attention (TF32). Block = 128 query rows of one (b,h).
// 8 warps; warp w owns rows 16w..16w+15. Key insight: q,k are unit vectors,
// so |score| <= 0.125 -> softmax needs NO max subtraction / online rescale.
// O accumulates in wmma frags across all key tiles; l[row] = sum of exp.
// ---------------------------------------------------------------------------
#define AP 72   // padded row pitch (floats)
#define ATT_SMEM ((128*AP + 64*AP + 64*AP + 128*AP + 128) * 4)

__global__ void __launch_bounds__(256) attn_tc_kernel(
    const float* __restrict__ qkv, float* __restrict__ outp)
{
    extern __shared__ float sm[];
    float* Qs   = sm;                  // 128 x AP
    float* Ks   = Qs + 128*AP;         // 64 x AP
    float* Vs   = Ks + 64*AP;          // 64 x AP
    float* Ps   = Vs + 64*AP;          // 128 x AP
    float* lrow = Ps + 128*AP;         // 128

    const int tid  = threadIdx.x;
    const int w    = tid >> 5;
    const int lane = tid & 31;

    const int qt = blockIdx.x & 15;            // T/128 = 16 q tiles
    const int h  = (blockIdx.x >> 4) & (Hn-1);
    const int b  = blockIdx.x >> 8;
    const int q0 = qt * 128;

    const float* qbase = qkv + (size_t)(b*Tn) * QKVN + h*HDn;
    const float* kbase = qbase + Dn;
    const float* vbase = qbase + 2*Dn;

    // Load Q tile, scale by 1/sqrt(HD), convert tf32.
    {
        const int r  = tid >> 1;
        const int c0 = (tid & 1) * 32;
        const float* src = qbase + (size_t)(q0 + r) * QKVN + c0;
        float* dst = Qs + r*AP + c0;
        #pragma unroll
        for (int j = 0; j < 8; j++) {
            float4 v = *(const float4*)(src + j*4);
            dst[j*4+0] = to_tf32(0.125f * v.x);
            dst[j*4+1] = to_tf32(0.125f * v.y);
            dst[j*4+2] = to_tf32(0.125f * v.z);
            dst[j*4+3] = to_tf32(0.125f * v.w);
        }
    }
    if (tid < 128) lrow[tid] = 0.f;

    wmma::fragment<wmma::accumulator, 16, 16, 8, float> oacc[4];
    #pragma unroll
    for (int j = 0; j < 4; j++) wmma::fill_fragment(oacc[j], 0.f);

    const int rowm = w * 16;

    for (int kt = 0; kt < Tn/64; kt++) {
        __syncthreads();   // prior tile's PV reads done
        {
            const int r  = tid >> 2;
            const int c0 = (tid & 3) * 16;
            const float* ks = kbase + (size_t)(kt*64 + r) * QKVN + c0;
            const float* vs = vbase + (size_t)(kt*64 + r) * QKVN + c0;
            float* kd = Ks + r*AP + c0;
            float* vd = Vs + r*AP + c0;
            #pragma unroll
            for (int j = 0; j < 4; j++) {
                float4 v = *(const float4*)(ks + j*4);
                kd[j*4+0] = to_tf32(v.x); kd[j*4+1] = to_tf32(v.y);
                kd[j*4+2] = to_tf32(v.z); kd[j*4+3] = to_tf32(v.w);
            }
            #pragma unroll
            for (int j = 0; j < 4; j++) {
                float4 v = *(const float4*)(vs + j*4);
                vd[j*4+0] = to_tf32(v.x); vd[j*4+1] = to_tf32(v.y);
                vd[j*4+2] = to_tf32(v.z); vd[j*4+3] = to_tf32(v.w);
            }
        }
        __syncthreads();

        // S = Q @ K^T   (K row-major [key][d] read as col-major [d][key])
        wmma::fragment<wmma::accumulator, 16, 16, 8, float> sacc[4];
        #pragma unroll
        for (int j = 0; j < 4; j++) wmma::fill_fragment(sacc[j], 0.f);
        #pragma unroll
        for (int ks = 0; ks < 8; ks++) {
            wmma::fragment<wmma::matrix_a, 16, 16, 8, wmma::precision::tf32, wmma::row_major> aq;
            wmma::load_matrix_sync(aq, Qs + rowm*AP + ks*8, AP);
            #pragma unroll
            for (int j = 0; j < 4; j++) {
                wmma::fragment<wmma::matrix_b, 16, 16, 8, wmma::precision::tf32, wmma::col_major> bk;
                wmma::load_matrix_sync(bk, Ks + j*16*AP + ks*8, AP);
                wmma::mma_sync(sacc[j], aq, bk, sacc[j]);
            }
        }
        #pragma unroll
        for (int j = 0; j < 4; j++)
            wmma::store_matrix_sync(Ps + rowm*AP + j*16, sacc[j], AP, wmma::mem_row_major);
        __syncwarp();

        // P = exp(S) (no max needed: |S| <= 0.125), accumulate row sums.
        {
            const int rr = rowm + (lane >> 1);
            const int cc = (lane & 1) * 32;
            float* pr = Ps + rr*AP + cc;
            float sum = 0.f;
            #pragma unroll
            for (int j = 0; j < 32; j++) {
                float e = __expf(pr[j]);
                sum += e;
                pr[j] = to_tf32(e);
            }
            sum += __shfl_xor_sync(0xffffffffu, sum, 1);
            if (!(lane & 1)) lrow[rr] += sum;
        }
        __syncwarp();

        // O += P @ V
        #pragma unroll
        for (int ks = 0; ks < 8; ks++) {
            wmma::fragment<wmma::matrix_a, 16, 16, 8, wmma::precision::tf32, wmma::row_major> ap;
            wmma::load_matrix_sync(ap, Ps + rowm*AP + ks*8, AP);
            #pragma unroll
            for (int j = 0; j < 4; j++) {
                wmma::fragment<wmma::matrix_b, 16, 16, 8, wmma::precision::tf32, wmma::row_major> bv;
                wmma::load_matrix_sync(bv, Vs + ks*8*AP + j*16, AP);
                wmma::mma_sync(oacc[j], ap, bv, oacc[j]);
            }
        }
    }

    __syncthreads();
    #pragma unroll
    for (int j = 0; j < 4; j++)
        wmma::store_matrix_sync(Ps + rowm*AP + j*16, oacc[j], AP, wmma::mem_row_major);
    __syncthreads();

    {
        const int r  = tid >> 1;
        const int c0 = (tid & 1) * 32;
        const float inv = 1.f / lrow[r];
        const float* srcr = Ps + r*AP + c0;
        float* dst = outp + (size_t)(b*Tn + q0 + r) * Dn + h*HDn + c0;
        #pragma unroll
        for (int j = 0; j < 8; j++) {
            float4 v;
            v.x = srcr[j*4+0] * inv; v.y = srcr[j*4+1] * inv;
            v.z = srcr[j*4+2] * inv; v.w = srcr[j*4+3] * inv;
            *(float4*)(dst + j*4) = v;
        }
    }
}

// ---------------------------------------------------------------------------
extern "C" void kernel_launch(void* const* d_in, const int* in_sizes, int n_in,
                              void* d_out, int out_size)
{
    const float* x    = (const float*)d_in[0];
    const float* Wqkv = (const float*)d_in[1];
    const float* Wo   = (const float*)d_in[2];
    const float* bo   = (const float*)d_in[3];
    float* out = (float*)d_out;

    float* qkv = nullptr;
    float* att = nullptr;
    cudaGetSymbolAddress((void**)&qkv, g_qkv);
    cudaGetSymbolAddress((void**)&att, g_attn);

    cudaFuncSetAttribute(attn_tc_kernel,
                         cudaFuncAttributeMaxDynamicSharedMemorySize, ATT_SMEM);

    // 1) qkv = x @ Wqkv   (tf32 tensor cores)
    {
        dim3 grid(QKVN/128, MROWS/128);
        gemm_tf32<<<grid, 256>>>(x, Wqkv, qkv, MROWS, QKVN, Dn);
    }
    // 2) RoPE + L2 norm on q,k
    {
        int warps = Bn*Tn*Hn*2;
        rope_norm_kernel<<<warps/8, 256>>>(qkv);
    }
    // 3) attention (tf32 tensor cores, no-max softmax)
    {
        dim3 grid(Bn * Hn * (Tn/128));   // 1024
        attn_tc_kernel<<<grid, 256, ATT_SMEM>>>(qkv, att);
    }
    // 4) out = att @ Wo + bo
    {
        dim3 grid(Dn/128, MROWS/128);
        gemm_tf32<<<grid, 256>>>(att, Wo, out, MROWS, Dn, Dn);
        int total4 = MROWS * Dn / 4;
        bias_add_kernel<<<(total4 + 255)/256, 256>>>(out, bo, total4, Dn);
    }
}